// round 15
// baseline (speedup 1.0000x reference)
#include <cuda_runtime.h>
#include <cuda_bf16.h>
#include <cuda_fp16.h>
#include <cstdint>
#include <math.h>

// ---------------------------------------------------------------------------
// QuantizedConv2d: N=32, Cin=128, H=W=56, Cout=256, 3x3, stride 1, pad 1
// pad value = IN_ZP = 3. Per-channel requant epilogue, float32 output.
//
// Round 15: R13 (best, 139.6us) with the serial probe kernel ELIMINATED.
// Dtype detection is inlined into the pack kernels (warp-parallel, per-block,
// amortized across SMs); pack_w block 0 also runs the bias/scale prep.
// Conv and pack bodies are byte-identical to R13.
// ---------------------------------------------------------------------------

#define N_    32
#define CIN   128
#define H_    56
#define W_    56
#define COUT  256
#define HW    (H_ * W_)
#define HP    58
#define WP    58

#define BM 128
#define BN 128
#define STAGES 9               // one per 3x3 tap, 128 B of K each
#define PITCH 144              // 128 B data + 16 B pad per row
#define STAGE_BYTES (256 * PITCH)          // A 128 rows + B 128 rows
#define SMEM_TOTAL (3 * STAGE_BYTES)       // 110592 B dynamic

// dtype codes: 0=int8, 1=int32, 2=float32, 3=bf16, 4=f16, 5=f64
__device__ int g_bias[COUT];
__device__ float g_scale[COUT];

__device__ int8_t g_xpad[(size_t)N_ * HP * WP * CIN];   // NHWC padded, pad = 3
__device__ int8_t g_wt[(size_t)9 * COUT * CIN];         // [kpos][cout][cin]

// ---------------------------------------------------------------------------
__device__ __forceinline__ float bf_val(uint32_t h) { return __int_as_float(h << 16); }
__device__ __forceinline__ float h_val(uint32_t h) {
    return __half2float(__ushort_as_half((unsigned short)h));
}
__device__ __forceinline__ bool int_ok(float g) { return g == rintf(g) && fabsf(g) <= 4096.f; }
__device__ __forceinline__ bool sc_ok(float g) { return g > 1e-5f && g < 0.5f; }

// Warp-collective probe: counts the 9 dtype/scale criteria over NW words.
// After return, every lane holds the full sums (shfl-xor reduction).
__device__ __forceinline__ void probe_counts(const uint32_t* buf, int NW,
                                             int lane, int cnt[9]) {
    const int per = NW >> 5;                  // words per lane
#pragma unroll
    for (int c = 0; c < 9; c++) cnt[c] = 0;
    for (int i = 0; i < per; i++) {
        uint32_t u = buf[lane * per + i];
        float f = __int_as_float(u);
        uint32_t hi = u >> 16, lo = u & 0xFFFFu;
        if (u == 0u || int_ok(f)) cnt[0]++;
        { int s = (int)u; if (s >= -4096 && s <= 4096) cnt[1]++; }
        if ((hi == 0u || int_ok(bf_val(hi))) && (lo == 0u || int_ok(bf_val(lo)))) cnt[2]++;
        if ((hi == 0u || int_ok(h_val(hi))) && (lo == 0u || int_ok(h_val(lo)))) cnt[3]++;
        if (sc_ok(f)) cnt[5]++;
        if (sc_ok(bf_val(hi)) && sc_ok(bf_val(lo))) cnt[6]++;
        if (sc_ok(h_val(hi)) && sc_ok(h_val(lo))) cnt[7]++;
    }
    const double* bufd = (const double*)buf;
    for (int i = 0; i < (per >> 1); i++) {
        double d = bufd[lane * (per >> 1) + i];
        if (d == rint(d) && fabs(d) <= 4096.0) cnt[4]++;
        if (d > 1e-5 && d < 0.5) cnt[8]++;
    }
#pragma unroll
    for (int c = 0; c < 9; c++)
#pragma unroll
        for (int o = 16; o > 0; o >>= 1)
            cnt[c] += __shfl_xor_sync(0xFFFFFFFFu, cnt[c], o);
}

__device__ __forceinline__ int dt_from(const int cnt[9], int NW) {
    int th = NW - NW / 16, th2 = NW / 2 - NW / 32;
    return (cnt[0] >= th) ? 2 : (cnt[1] >= th) ? 1 : (cnt[2] >= th) ? 3
         : (cnt[3] >= th) ? 4 : (cnt[4] >= th2) ? 5 : 0;
}
__device__ __forceinline__ int scl_from(const int cnt[9], int NW) {
    int th = NW - NW / 16, th2 = NW / 2 - NW / 32;
    return (cnt[5] >= th) || (cnt[6] >= th) || (cnt[7] >= th) || (cnt[8] >= th2);
}
__device__ __forceinline__ int sdt_from(const int cnt[9], int NW) {
    int th = NW - NW / 16, th2 = NW / 2 - NW / 32;
    return (cnt[5] >= th) ? 2 : (cnt[6] >= th) ? 3 : (cnt[7] >= th) ? 4
         : (cnt[8] >= th2) ? 5 : 2;
}

__device__ __forceinline__ int8_t load_elem(const void* p, int dt, size_t i) {
    if (dt == 2) return (int8_t)(int)rintf(((const float*)p)[i]);
    if (dt == 1) return (int8_t)((const int*)p)[i];
    if (dt == 3) return (int8_t)(int)rintf(__bfloat162float(((const __nv_bfloat16*)p)[i]));
    if (dt == 4) return (int8_t)(int)rintf(__half2float(((const __half*)p)[i]));
    if (dt == 5) return (int8_t)(int)rint(((const double*)p)[i]);
    return ((const int8_t*)p)[i];
}

// NCHW (any dtype) -> padded NHWC int8; one block per (n, 2 rows of h).
// Also writes the pad border (value 3). Dtype of x detected inline (warp 0).
__global__ __launch_bounds__(512)
void pack_x_kernel(const void* xv) {
    __shared__ int8_t s[2][CIN * 57];
    __shared__ int s_dtx;
    int nh2 = blockIdx.x;           // n * 28 + h2
    int n = nh2 / 28, h2 = nh2 % 28;
    int h0 = h2 * 2;
    int t = threadIdx.x;            // 512

    // ---- inline dtype probe (warp 0) ----
    if (t < 32) {
        int cnt[9];
        probe_counts((const uint32_t*)xv, 256, t, cnt);
        if (t == 0) s_dtx = dt_from(cnt, 256);
    }

    // ---- border pads (independent of dtype) ----
    int4 pv; pv.x = pv.y = pv.z = pv.w = 0x03030303;
    if (t >= 32 && t < 64) {        // w=0 / w=57 pads for this block's 2 rows
        int tt = t - 32;
        int row = tt >> 4;
        int side = (tt >> 3) & 1;
        int k = tt & 7;
        size_t off = ((size_t)(n * HP + h0 + row + 1) * WP + side * 57) * CIN
                     + (size_t)k * 16;
        *(int4*)(g_xpad + off) = pv;
    }
    if (h2 == 0 || h2 == 27) {      // full pad row h=0 or h=57
        int hsel = (h2 == 0) ? 0 : 57;
        size_t base = (size_t)(n * HP + hsel) * WP * CIN;
        for (int i = t; i < 464; i += 512)
            *(int4*)(g_xpad + base + (size_t)i * 16) = pv;
    }
    __syncthreads();
    const int dt = s_dtx;

    if (dt == 2) {
        const float4* xf = (const float4*)xv;
        for (int idx = t; idx < 2 * CIN * 14; idx += 512) {
            int row = idx / (CIN * 14), r = idx % (CIN * 14);
            int ci = r / 14, w4 = r % 14;
            float4 v = xf[((size_t)(n * CIN + ci) * H_ + h0 + row) * 14 + w4];
            int8_t* sp = s[row] + ci * 57 + w4 * 4;
            sp[0] = (int8_t)(int)rintf(v.x);
            sp[1] = (int8_t)(int)rintf(v.y);
            sp[2] = (int8_t)(int)rintf(v.z);
            sp[3] = (int8_t)(int)rintf(v.w);
        }
    } else {
        for (int idx = t; idx < 2 * CIN * W_; idx += 512) {
            int row = idx / (CIN * W_), r = idx % (CIN * W_);
            int ci = r / W_, w = r % W_;
            size_t gi = ((size_t)(n * CIN + ci) * H_ + h0 + row) * W_ + w;
            s[row][ci * 57 + w] = load_elem(xv, dt, gi);
        }
    }
    __syncthreads();

    for (int idx = t; idx < 2 * W_ * (CIN / 4); idx += 512) {
        int row = idx / (W_ * 32), r = idx % (W_ * 32);
        int w = r / 32, c4 = r % 32;
        const int8_t* sr = s[row];
        unsigned b0 = (unsigned char)sr[(c4 * 4 + 0) * 57 + w];
        unsigned b1 = (unsigned char)sr[(c4 * 4 + 1) * 57 + w];
        unsigned b2 = (unsigned char)sr[(c4 * 4 + 2) * 57 + w];
        unsigned b3 = (unsigned char)sr[(c4 * 4 + 3) * 57 + w];
        int8_t* dst = g_xpad + ((size_t)(n * HP + h0 + row + 1) * WP + 1) * CIN;
        *(unsigned*)(dst + (size_t)w * CIN + c4 * 4) = b0 | (b1 << 8) | (b2 << 16) | (b3 << 24);
    }
}

// OIHW (any dtype) -> [kpos][cout][cin] int8, coalesced reads + smem transpose.
// Dtype of w detected inline (warp 0). Block 0 additionally probes the two
// 256-elem buffers (warps 2 & 3) and runs the bias/scale prep.
__global__ __launch_bounds__(256)
void pack_w_kernel(const void* wv, const void* ap, const void* bp) {
    __shared__ int8_t sw[2][9][CIN];
    __shared__ int s_dtw;
    __shared__ int s_a[3], s_b[3];      // {dt, scl, sdt} for ap and bp
    int co0 = blockIdx.x * 2;
    int t = threadIdx.x;
    int warp = t >> 5, lane = t & 31;

    if (warp == 0) {
        int cnt[9];
        probe_counts((const uint32_t*)wv, 256, lane, cnt);
        if (lane == 0) s_dtw = dt_from(cnt, 256);
    }
    if (blockIdx.x == 0) {
        if (warp == 2) {
            int cnt[9];
            probe_counts((const uint32_t*)ap, 64, lane, cnt);
            if (lane == 0) {
                s_a[0] = dt_from(cnt, 64);
                s_a[1] = scl_from(cnt, 64);
                s_a[2] = sdt_from(cnt, 64);
            }
        }
        if (warp == 3) {
            int cnt[9];
            probe_counts((const uint32_t*)bp, 64, lane, cnt);
            if (lane == 0) {
                s_b[0] = dt_from(cnt, 64);
                s_b[1] = scl_from(cnt, 64);
                s_b[2] = sdt_from(cnt, 64);
            }
        }
    }
    __syncthreads();
    const int dt = s_dtw;

    // ---- block 0: bias/scale prep (identical math to R13) ----
    if (blockIdx.x == 0) {
        int swap = (s_a[1] && !s_b[1]) ? 1 : 0;
        int dtb = swap ? s_b[0] : s_a[0];
        int dtsv = swap ? s_a[2] : s_b[2];
        const void* BP = swap ? bp : ap;
        const void* WS = swap ? ap : bp;
        int i = t;
        int v;
        if (dtb == 2)      v = (int)rintf(((const float*)BP)[i]);
        else if (dtb == 3) v = (int)rintf(__bfloat162float(((const __nv_bfloat16*)BP)[i]));
        else if (dtb == 4) v = (int)rintf(__half2float(((const __half*)BP)[i]));
        else if (dtb == 5) v = (int)rint(((const double*)BP)[i]);
        else               v = ((const int*)BP)[i];
        g_bias[i] = v;

        float wsv;
        if (dtsv == 3)      wsv = __bfloat162float(((const __nv_bfloat16*)WS)[i]);
        else if (dtsv == 4) wsv = __half2float(((const __half*)WS)[i]);
        else if (dtsv == 5) wsv = (float)((const double*)WS)[i];
        else                wsv = ((const float*)WS)[i];
        g_scale[i] = __fdiv_rn(__fmul_rn(0.05f, wsv), 0.1f);   // reference op order
    }

    // ---- pack (byte-identical to R13) ----
    if (dt == 2) {
        const float4* wf = (const float4*)wv;
        for (int i = t; i < 576; i += 256) {
            int cl = i / 288, i4 = i % 288;
            float4 v = wf[(size_t)(co0 + cl) * 288 + i4];
            float vv[4] = {v.x, v.y, v.z, v.w};
            int e = i4 * 4;
#pragma unroll
            for (int j = 0; j < 4; j++) {
                int e2 = e + j;
                sw[cl][e2 % 9][e2 / 9] = (int8_t)(int)rintf(vv[j]);
            }
        }
    } else {
        for (int i = t; i < 2304; i += 256) {
            int cl = i / 1152, e = i % 1152;
            sw[cl][e % 9][e / 9] = load_elem(wv, dt, (size_t)(co0 + cl) * 1152 + e);
        }
    }
    __syncthreads();

    if (t < 144) {
        int cl = t / 72, r = t % 72;
        int kp = r / 8, c16 = r % 8;
        int4 v = *(const int4*)&sw[cl][kp][c16 * 16];
        *(int4*)(g_wt + (size_t)kp * (COUT * CIN) + (size_t)(co0 + cl) * CIN
                 + (size_t)c16 * 16) = v;
    }
}

// ---------------------------------------------------------------------------
__device__ __forceinline__ void cpasync16(uint32_t smem, const void* gptr) {
    asm volatile("cp.async.cg.shared.global [%0], [%1], 16;\n" :: "r"(smem), "l"(gptr));
}

__device__ __forceinline__ void ldsm4(uint32_t& r0, uint32_t& r1, uint32_t& r2, uint32_t& r3,
                                      uint32_t addr) {
    asm volatile("ldmatrix.sync.aligned.m8n8.x4.shared.b16 {%0,%1,%2,%3}, [%4];"
                 : "=r"(r0), "=r"(r1), "=r"(r2), "=r"(r3) : "r"(addr));
}

__device__ __forceinline__ void mma_s8(int* c, uint32_t a0, uint32_t a1, uint32_t a2, uint32_t a3,
                                       uint32_t b0, uint32_t b1) {
    asm volatile(
        "mma.sync.aligned.m16n8k32.row.col.s32.s8.s8.s32 "
        "{%0,%1,%2,%3}, {%4,%5,%6,%7}, {%8,%9}, {%0,%1,%2,%3};"
        : "+r"(c[0]), "+r"(c[1]), "+r"(c[2]), "+r"(c[3])
        : "r"(a0), "r"(a1), "r"(a2), "r"(a3), "r"(b0), "r"(b1));
}

__global__ __launch_bounds__(256, 2)
void conv_kernel(float* __restrict__ out) {
    extern __shared__ __align__(16) uint8_t smem_raw[];

    const int t = threadIdx.x;
    const int lane = t & 31;
    const int warp = t >> 5;           // 0..7
    const int wm = warp >> 2;          // 0..1 : 64-pixel half
    const int wn = warp & 3;           // 0..3 : 32-cout quarter
    const int g = lane >> 2;           // 0..7
    const int tig = lane & 3;          // 0..3
    const int p0 = blockIdx.x * BM;
    const int co0 = blockIdx.y * BN;

    const uint32_t smbase = (uint32_t)__cvta_generic_to_shared(smem_raw);

    // ---- cp.async coordinates: q = 16B chunk (0..7), base row 0..31,
    //      each thread covers rows base, +32, +64, +96 for A and B ----
    const int q = t & 7;
    const int row0 = t >> 3;           // 0..31
    int arow[4], brow[4];
#pragma unroll
    for (int i = 0; i < 4; i++) {
        int row = row0 + i * 32;
        int p = p0 + row;
        int n = p / HW;
        int hw = p % HW;
        int h = hw / W_, w = hw % W_;
        arow[i] = ((n * HP + h) * WP + w) * CIN + q * 16;
        brow[i] = (co0 + row) * CIN + q * 16;
    }
    const uint32_t s_off = (uint32_t)(row0 * PITCH + q * 16);

    // ---- ldmatrix per-thread base offsets (bytes) ----
    const uint32_t a_toff = (uint32_t)((wm * 64 + (lane & 15)) * PITCH + (lane >> 4) * 16);
    const uint32_t b_toff = (uint32_t)((wn * 32 + ((lane >> 4) & 1) * 8 + (lane & 7)) * PITCH
                                       + ((lane >> 3) & 1) * 16);

    int acc[4][4][4] = {};             // [mi][nj][reg]

#define ABUF(b) (smbase + (uint32_t)(b) * STAGE_BYTES)
#define BBUF(b) (smbase + (uint32_t)(b) * STAGE_BYTES + (uint32_t)(128 * PITCH))

#define LOAD_STAGE(S, BUF)                                                        \
    do {                                                                          \
        int kpos_ = (S);                                                          \
        int aoff_ = ((kpos_ / 3) * WP + kpos_ % 3) * CIN;                         \
        int boff_ = kpos_ * (COUT * CIN);                                         \
        uint32_t ab_ = ABUF(BUF) + s_off;                                         \
        uint32_t bb_ = BBUF(BUF) + s_off;                                         \
        _Pragma("unroll")                                                         \
        for (int i_ = 0; i_ < 4; i_++)                                            \
            cpasync16(ab_ + (uint32_t)(i_ * 32 * PITCH), g_xpad + arow[i_] + aoff_); \
        _Pragma("unroll")                                                         \
        for (int i_ = 0; i_ < 4; i_++)                                            \
            cpasync16(bb_ + (uint32_t)(i_ * 32 * PITCH), g_wt + brow[i_] + boff_);   \
        asm volatile("cp.async.commit_group;\n");                                 \
    } while (0)

    LOAD_STAGE(0, 0);
    LOAD_STAGE(1, 1);

#pragma unroll 1
    for (int s = 0; s < STAGES; s++) {
        if (s < STAGES - 1)
            asm volatile("cp.async.wait_group 1;\n");
        else
            asm volatile("cp.async.wait_group 0;\n");
        __syncthreads();               // stage s visible; stage s-1 consumers done

        if (s + 2 < STAGES)
            LOAD_STAGE(s + 2, (s + 2) % 3);

        const int buf = s % 3;
        const uint32_t Ab = ABUF(buf) + a_toff;
        const uint32_t Bb = BBUF(buf) + b_toff;

#pragma unroll
        for (int ks = 0; ks < 4; ks++) {
            uint32_t a[4][4];
#pragma unroll
            for (int mi = 0; mi < 4; mi++)
                ldsm4(a[mi][0], a[mi][1], a[mi][2], a[mi][3],
                      Ab + (uint32_t)(mi * 16 * PITCH + ks * 32));
            uint32_t bfr[2][4];
#pragma unroll
            for (int p = 0; p < 2; p++)
                ldsm4(bfr[p][0], bfr[p][1], bfr[p][2], bfr[p][3],
                      Bb + (uint32_t)(p * 16 * PITCH + ks * 32));
#pragma unroll
            for (int mi = 0; mi < 4; mi++)
#pragma unroll
                for (int nj = 0; nj < 4; nj++) {
                    const uint32_t* bp = bfr[nj >> 1];
                    uint32_t b0 = (nj & 1) ? bp[2] : bp[0];
                    uint32_t b1 = (nj & 1) ? bp[3] : bp[1];
                    mma_s8(acc[mi][nj], a[mi][0], a[mi][1], a[mi][2], a[mi][3], b0, b1);
                }
        }
    }

    // ---- epilogue: requant, float32 output, direct stores ----
    float sc[4][2];
    int bi[4][2];
#pragma unroll
    for (int nj = 0; nj < 4; nj++) {
        int co = co0 + wn * 32 + nj * 8 + tig * 2;
#pragma unroll
        for (int e = 0; e < 2; e++) {
            bi[nj][e] = g_bias[co + e];
            sc[nj][e] = g_scale[co + e];
        }
    }

#pragma unroll
    for (int mi = 0; mi < 4; mi++) {
        int pixbase = p0 + wm * 64 + mi * 16;
#pragma unroll
        for (int half = 0; half < 2; half++) {
            int pix = pixbase + g + half * 8;
            int n = pix / HW, sp = pix % HW;
            size_t obase = (size_t)n * (COUT * HW) + sp;
#pragma unroll
            for (int nj = 0; nj < 4; nj++) {
                int co = co0 + wn * 32 + nj * 8 + tig * 2;
#pragma unroll
                for (int e = 0; e < 2; e++) {
                    int a = acc[mi][nj][half * 2 + e] + bi[nj][e];
                    float y = __fadd_rn(__fmul_rn((float)a, sc[nj][e]), -2.0f);
                    y = rintf(y);
                    y = fminf(fmaxf(y, -128.0f), 127.0f);
                    out[obase + (size_t)(co + e) * HW] = y;
                }
            }
        }
    }
#undef ABUF
#undef BBUF
#undef LOAD_STAGE
}

// ---------------------------------------------------------------------------
extern "C" void kernel_launch(void* const* d_in, const int* in_sizes, int n_in,
                              void* d_out, int out_size) {
    int idx_sorted[8];
    int n = (n_in < 8) ? n_in : 8;
    for (int i = 0; i < n; i++) idx_sorted[i] = i;
    for (int i = 0; i < n; i++)
        for (int j = i + 1; j < n; j++)
            if (in_sizes[idx_sorted[j]] > in_sizes[idx_sorted[i]]) {
                int tmp = idx_sorted[i]; idx_sorted[i] = idx_sorted[j]; idx_sorted[j] = tmp;
            }
    const void* x = d_in[idx_sorted[0]];
    const void* w = d_in[idx_sorted[1]];
    int ia = idx_sorted[2], ib = idx_sorted[3];
    if (ia > ib) { int tmp = ia; ia = ib; ib = tmp; }
    const void* ap = d_in[ia];
    const void* bp = d_in[ib];

    static int smem_set = 0;
    if (!smem_set) {
        cudaFuncSetAttribute(conv_kernel, cudaFuncAttributeMaxDynamicSharedMemorySize,
                             SMEM_TOTAL);
        smem_set = 1;
    }

    pack_w_kernel<<<COUT / 2, 256>>>(w, ap, bp);
    pack_x_kernel<<<N_ * 28, 512>>>(x);

    dim3 grid((N_ * HW) / BM, COUT / BN);   // (784, 2)
    conv_kernel<<<grid, 256, SMEM_TOTAL>>>((float*)d_out);
}

// round 16
// speedup vs baseline: 1.0864x; 1.0864x over previous
#include <cuda_runtime.h>
#include <cuda_bf16.h>
#include <cuda_fp16.h>
#include <cstdint>
#include <math.h>

// ---------------------------------------------------------------------------
// QuantizedConv2d: N=32, Cin=128, H=W=56, Cout=256, 3x3, stride 1, pad 1
// pad value = IN_ZP = 3. Per-channel requant epilogue, float32 output.
//
// Round 16: R13 (best, 139.6us) with ONE contained change: pack_x phase 2
// uses u32 loads + byte_perm 4x4 transposes (smem ci-row stride 57B -> 60B).
// Probe, pack_w, conv byte-identical to R13.
// ---------------------------------------------------------------------------

#define N_    32
#define CIN   128
#define H_    56
#define W_    56
#define COUT  256
#define HW    (H_ * W_)
#define HP    58
#define WP    58

#define BM 128
#define BN 128
#define STAGES 9               // one per 3x3 tap, 128 B of K each
#define PITCH 144              // 128 B data + 16 B pad per row
#define STAGE_BYTES (256 * PITCH)          // A 128 rows + B 128 rows
#define SMEM_TOTAL (3 * STAGE_BYTES)       // 110592 B dynamic

// dtype codes: 0=int8, 1=int32, 2=float32, 3=bf16, 4=f16, 5=f64
__device__ int g_dt_x, g_dt_w, g_dt_b, g_dt_s, g_swap;
__device__ int g_bias[COUT];
__device__ float g_scale[COUT];

__device__ int8_t g_xpad[(size_t)N_ * HP * WP * CIN];   // NHWC padded, pad = 3
__device__ int8_t g_wt[(size_t)9 * COUT * CIN];         // [kpos][cout][cin]

// ---------------------------------------------------------------------------
__device__ __forceinline__ float bf_val(uint32_t h) { return __int_as_float(h << 16); }
__device__ __forceinline__ float h_val(uint32_t h) {
    return __half2float(__ushort_as_half((unsigned short)h));
}
__device__ __forceinline__ bool int_ok(float g) { return g == rintf(g) && fabsf(g) <= 4096.f; }
__device__ __forceinline__ bool sc_ok(float g) { return g > 1e-5f && g < 0.5f; }

// Warp-parallel probe: warp b probes buffer b (shfl-reduced counts, no atomics),
// then one barrier, then 256-thread bias/scale prep.  (R13 verbatim)
__global__ void probe_prep_kernel(const void* xp, const void* wp,
                                  const void* ap, const void* bp) {
    __shared__ int s_dt[4], s_scl[4], s_sdt[4];
    int t = threadIdx.x;
    int warp = t >> 5, lane = t & 31;

    if (warp < 4) {
        const void* bufs[4] = {xp, wp, ap, bp};
        const uint32_t* buf = (const uint32_t*)bufs[warp];
        const int NW = (warp < 2) ? 256 : 64;
        const int per = NW >> 5;              // words per lane: 8 or 2

        int cnt[9] = {0, 0, 0, 0, 0, 0, 0, 0, 0};
        for (int i = 0; i < per; i++) {
            uint32_t u = buf[lane * per + i];
            float f = __int_as_float(u);
            uint32_t hi = u >> 16, lo = u & 0xFFFFu;
            if (u == 0u || int_ok(f)) cnt[0]++;
            { int s = (int)u; if (s >= -4096 && s <= 4096) cnt[1]++; }
            if ((hi == 0u || int_ok(bf_val(hi))) && (lo == 0u || int_ok(bf_val(lo)))) cnt[2]++;
            if ((hi == 0u || int_ok(h_val(hi))) && (lo == 0u || int_ok(h_val(lo)))) cnt[3]++;
            if (sc_ok(f)) cnt[5]++;
            if (sc_ok(bf_val(hi)) && sc_ok(bf_val(lo))) cnt[6]++;
            if (sc_ok(h_val(hi)) && sc_ok(h_val(lo))) cnt[7]++;
        }
        const double* bufd = (const double*)buf;
        for (int i = 0; i < (per >> 1); i++) {
            double d = bufd[lane * (per >> 1) + i];
            if (d == rint(d) && fabs(d) <= 4096.0) cnt[4]++;
            if (d > 1e-5 && d < 0.5) cnt[8]++;
        }
#pragma unroll
        for (int c = 0; c < 9; c++)
#pragma unroll
            for (int o = 16; o > 0; o >>= 1)
                cnt[c] += __shfl_down_sync(0xFFFFFFFFu, cnt[c], o);

        if (lane == 0) {
            int th = NW - NW / 16, th2 = NW / 2 - NW / 32;
            s_dt[warp] = (cnt[0] >= th) ? 2 : (cnt[1] >= th) ? 1 : (cnt[2] >= th) ? 3
                       : (cnt[3] >= th) ? 4 : (cnt[4] >= th2) ? 5 : 0;
            s_scl[warp] = (cnt[5] >= th) || (cnt[6] >= th) || (cnt[7] >= th) || (cnt[8] >= th2);
            s_sdt[warp] = (cnt[5] >= th) ? 2 : (cnt[6] >= th) ? 3 : (cnt[7] >= th) ? 4
                        : (cnt[8] >= th2) ? 5 : 2;
        }
    }
    __syncthreads();

    int swap = (s_scl[2] && !s_scl[3]) ? 1 : 0;
    int dtb = swap ? s_dt[3] : s_dt[2];
    int dtsv = swap ? s_sdt[2] : s_sdt[3];
    if (t == 0) {
        g_dt_x = s_dt[0];
        g_dt_w = s_dt[1];
        g_swap = swap;
        g_dt_b = dtb;
        g_dt_s = dtsv;
    }

    // ---- prep bias + scale (one channel per thread) ----
    const void* BP = swap ? bp : ap;
    const void* WS = swap ? ap : bp;
    int i = t;
    int v;
    if (dtb == 2)      v = (int)rintf(((const float*)BP)[i]);
    else if (dtb == 3) v = (int)rintf(__bfloat162float(((const __nv_bfloat16*)BP)[i]));
    else if (dtb == 4) v = (int)rintf(__half2float(((const __half*)BP)[i]));
    else if (dtb == 5) v = (int)rint(((const double*)BP)[i]);
    else               v = ((const int*)BP)[i];
    g_bias[i] = v;

    float wsv;
    if (dtsv == 3)      wsv = __bfloat162float(((const __nv_bfloat16*)WS)[i]);
    else if (dtsv == 4) wsv = __half2float(((const __half*)WS)[i]);
    else if (dtsv == 5) wsv = (float)((const double*)WS)[i];
    else                wsv = ((const float*)WS)[i];
    g_scale[i] = __fdiv_rn(__fmul_rn(0.05f, wsv), 0.1f);   // reference op order
}

__device__ __forceinline__ int8_t load_elem(const void* p, int dt, size_t i) {
    if (dt == 2) return (int8_t)(int)rintf(((const float*)p)[i]);
    if (dt == 1) return (int8_t)((const int*)p)[i];
    if (dt == 3) return (int8_t)(int)rintf(__bfloat162float(((const __nv_bfloat16*)p)[i]));
    if (dt == 4) return (int8_t)(int)rintf(__half2float(((const __half*)p)[i]));
    if (dt == 5) return (int8_t)(int)rint(((const double*)p)[i]);
    return ((const int8_t*)p)[i];
}

// NCHW (any dtype) -> padded NHWC int8; one block per (n, 2 rows of h).
// Also writes the pad border (value 3).
// smem: per h-row, 128 ci-rows of 15 u32 (60 B; bytes 0..55 = w values).
// Phase 2: u32 loads + byte_perm 4x4 transposes, coalesced u32 stores.
__global__ __launch_bounds__(512)
void pack_x_kernel(const void* xv) {
    __shared__ uint32_t su[2][CIN * 15];   // 15360 B
    int nh2 = blockIdx.x;           // n * 28 + h2
    int n = nh2 / 28, h2 = nh2 % 28;
    int h0 = h2 * 2;
    int t = threadIdx.x;            // 512
    int dt = g_dt_x;

    int4 pv; pv.x = pv.y = pv.z = pv.w = 0x03030303;
    if (t < 32) {                   // w=0 / w=57 pads for this block's 2 rows
        int row = t >> 4;
        int side = (t >> 3) & 1;
        int k = t & 7;
        size_t off = ((size_t)(n * HP + h0 + row + 1) * WP + side * 57) * CIN
                     + (size_t)k * 16;
        *(int4*)(g_xpad + off) = pv;
    }
    if (h2 == 0 || h2 == 27) {      // full pad row h=0 or h=57
        int hsel = (h2 == 0) ? 0 : 57;
        size_t base = (size_t)(n * HP + hsel) * WP * CIN;
        for (int i = t; i < 464; i += 512)
            *(int4*)(g_xpad + base + (size_t)i * 16) = pv;
    }

    // ---- phase 1: NCHW -> smem (u32-packed, 15-word ci rows) ----
    if (dt == 2) {
        const float4* xf = (const float4*)xv;
        for (int idx = t; idx < 2 * CIN * 14; idx += 512) {
            int row = idx / (CIN * 14), r = idx % (CIN * 14);
            int ci = r / 14, w4 = r % 14;
            float4 v = xf[((size_t)(n * CIN + ci) * H_ + h0 + row) * 14 + w4];
            uint32_t b0 = (uint32_t)(uint8_t)(int8_t)(int)rintf(v.x);
            uint32_t b1 = (uint32_t)(uint8_t)(int8_t)(int)rintf(v.y);
            uint32_t b2 = (uint32_t)(uint8_t)(int8_t)(int)rintf(v.z);
            uint32_t b3 = (uint32_t)(uint8_t)(int8_t)(int)rintf(v.w);
            su[row][ci * 15 + w4] = b0 | (b1 << 8) | (b2 << 16) | (b3 << 24);
        }
    } else {
        for (int idx = t; idx < 2 * CIN * W_; idx += 512) {
            int row = idx / (CIN * W_), r = idx % (CIN * W_);
            int ci = r / W_, w = r % W_;
            size_t gi = ((size_t)(n * CIN + ci) * H_ + h0 + row) * W_ + w;
            ((int8_t*)su[row])[ci * 60 + w] = load_elem(xv, dt, gi);
        }
    }
    __syncthreads();

    // ---- phase 2: 4x4 byte transposes ----
    // unit = ((row*14 + w4)*32 + cig): lanes span cig 0..31 -> coalesced stores
    for (int u = t; u < 896; u += 512) {
        int row = u / 448, r = u % 448;
        int w4 = r / 32, cig = r % 32;
        const uint32_t* sr = su[row] + cig * 60 + w4;   // ci0 = cig*4, stride 15
        uint32_t v0 = sr[0], v1 = sr[15], v2 = sr[30], v3 = sr[45];
        int8_t* dst = g_xpad + ((size_t)(n * HP + h0 + row + 1) * WP + 1) * CIN;
#pragma unroll
        for (int l = 0; l < 4; l++) {
            uint32_t sel = (uint32_t)l | ((uint32_t)(4 + l) << 4);
            uint32_t o = __byte_perm(__byte_perm(v0, v1, sel),
                                     __byte_perm(v2, v3, sel), 0x5410);
            ((uint32_t*)(dst + (size_t)(w4 * 4 + l) * CIN))[cig] = o;
        }
    }
}

// OIHW (any dtype) -> [kpos][cout][cin] int8, coalesced reads + smem transpose.
// (R13 verbatim)
__global__ void pack_w_kernel(const void* wv) {
    __shared__ int8_t sw[2][9][CIN];
    int co0 = blockIdx.x * 2;
    int t = threadIdx.x;
    int dt = g_dt_w;

    if (dt == 2) {
        const float4* wf = (const float4*)wv;
        for (int i = t; i < 576; i += 256) {
            int cl = i / 288, i4 = i % 288;
            float4 v = wf[(size_t)(co0 + cl) * 288 + i4];
            float vv[4] = {v.x, v.y, v.z, v.w};
            int e = i4 * 4;
#pragma unroll
            for (int j = 0; j < 4; j++) {
                int e2 = e + j;
                sw[cl][e2 % 9][e2 / 9] = (int8_t)(int)rintf(vv[j]);
            }
        }
    } else {
        for (int i = t; i < 2304; i += 256) {
            int cl = i / 1152, e = i % 1152;
            sw[cl][e % 9][e / 9] = load_elem(wv, dt, (size_t)(co0 + cl) * 1152 + e);
        }
    }
    __syncthreads();

    if (t < 144) {
        int cl = t / 72, r = t % 72;
        int kp = r / 8, c16 = r % 8;
        int4 v = *(const int4*)&sw[cl][kp][c16 * 16];
        *(int4*)(g_wt + (size_t)kp * (COUT * CIN) + (size_t)(co0 + cl) * CIN
                 + (size_t)c16 * 16) = v;
    }
}

// ---------------------------------------------------------------------------
__device__ __forceinline__ void cpasync16(uint32_t smem, const void* gptr) {
    asm volatile("cp.async.cg.shared.global [%0], [%1], 16;\n" :: "r"(smem), "l"(gptr));
}

__device__ __forceinline__ void ldsm4(uint32_t& r0, uint32_t& r1, uint32_t& r2, uint32_t& r3,
                                      uint32_t addr) {
    asm volatile("ldmatrix.sync.aligned.m8n8.x4.shared.b16 {%0,%1,%2,%3}, [%4];"
                 : "=r"(r0), "=r"(r1), "=r"(r2), "=r"(r3) : "r"(addr));
}

__device__ __forceinline__ void mma_s8(int* c, uint32_t a0, uint32_t a1, uint32_t a2, uint32_t a3,
                                       uint32_t b0, uint32_t b1) {
    asm volatile(
        "mma.sync.aligned.m16n8k32.row.col.s32.s8.s8.s32 "
        "{%0,%1,%2,%3}, {%4,%5,%6,%7}, {%8,%9}, {%0,%1,%2,%3};"
        : "+r"(c[0]), "+r"(c[1]), "+r"(c[2]), "+r"(c[3])
        : "r"(a0), "r"(a1), "r"(a2), "r"(a3), "r"(b0), "r"(b1));
}

__global__ __launch_bounds__(256, 2)
void conv_kernel(float* __restrict__ out) {
    extern __shared__ __align__(16) uint8_t smem_raw[];

    const int t = threadIdx.x;
    const int lane = t & 31;
    const int warp = t >> 5;           // 0..7
    const int wm = warp >> 2;          // 0..1 : 64-pixel half
    const int wn = warp & 3;           // 0..3 : 32-cout quarter
    const int g = lane >> 2;           // 0..7
    const int tig = lane & 3;          // 0..3
    const int p0 = blockIdx.x * BM;
    const int co0 = blockIdx.y * BN;

    const uint32_t smbase = (uint32_t)__cvta_generic_to_shared(smem_raw);

    // ---- cp.async coordinates: q = 16B chunk (0..7), base row 0..31,
    //      each thread covers rows base, +32, +64, +96 for A and B ----
    const int q = t & 7;
    const int row0 = t >> 3;           // 0..31
    int arow[4], brow[4];
#pragma unroll
    for (int i = 0; i < 4; i++) {
        int row = row0 + i * 32;
        int p = p0 + row;
        int n = p / HW;
        int hw = p % HW;
        int h = hw / W_, w = hw % W_;
        arow[i] = ((n * HP + h) * WP + w) * CIN + q * 16;
        brow[i] = (co0 + row) * CIN + q * 16;
    }
    const uint32_t s_off = (uint32_t)(row0 * PITCH + q * 16);

    // ---- ldmatrix per-thread base offsets (bytes) ----
    const uint32_t a_toff = (uint32_t)((wm * 64 + (lane & 15)) * PITCH + (lane >> 4) * 16);
    const uint32_t b_toff = (uint32_t)((wn * 32 + ((lane >> 4) & 1) * 8 + (lane & 7)) * PITCH
                                       + ((lane >> 3) & 1) * 16);

    int acc[4][4][4] = {};             // [mi][nj][reg]

#define ABUF(b) (smbase + (uint32_t)(b) * STAGE_BYTES)
#define BBUF(b) (smbase + (uint32_t)(b) * STAGE_BYTES + (uint32_t)(128 * PITCH))

#define LOAD_STAGE(S, BUF)                                                        \
    do {                                                                          \
        int kpos_ = (S);                                                          \
        int aoff_ = ((kpos_ / 3) * WP + kpos_ % 3) * CIN;                         \
        int boff_ = kpos_ * (COUT * CIN);                                         \
        uint32_t ab_ = ABUF(BUF) + s_off;                                         \
        uint32_t bb_ = BBUF(BUF) + s_off;                                         \
        _Pragma("unroll")                                                         \
        for (int i_ = 0; i_ < 4; i_++)                                            \
            cpasync16(ab_ + (uint32_t)(i_ * 32 * PITCH), g_xpad + arow[i_] + aoff_); \
        _Pragma("unroll")                                                         \
        for (int i_ = 0; i_ < 4; i_++)                                            \
            cpasync16(bb_ + (uint32_t)(i_ * 32 * PITCH), g_wt + brow[i_] + boff_);   \
        asm volatile("cp.async.commit_group;\n");                                 \
    } while (0)

    LOAD_STAGE(0, 0);
    LOAD_STAGE(1, 1);

#pragma unroll 1
    for (int s = 0; s < STAGES; s++) {
        if (s < STAGES - 1)
            asm volatile("cp.async.wait_group 1;\n");
        else
            asm volatile("cp.async.wait_group 0;\n");
        __syncthreads();               // stage s visible; stage s-1 consumers done

        if (s + 2 < STAGES)
            LOAD_STAGE(s + 2, (s + 2) % 3);

        const int buf = s % 3;
        const uint32_t Ab = ABUF(buf) + a_toff;
        const uint32_t Bb = BBUF(buf) + b_toff;

#pragma unroll
        for (int ks = 0; ks < 4; ks++) {
            uint32_t a[4][4];
#pragma unroll
            for (int mi = 0; mi < 4; mi++)
                ldsm4(a[mi][0], a[mi][1], a[mi][2], a[mi][3],
                      Ab + (uint32_t)(mi * 16 * PITCH + ks * 32));
            uint32_t bfr[2][4];
#pragma unroll
            for (int p = 0; p < 2; p++)
                ldsm4(bfr[p][0], bfr[p][1], bfr[p][2], bfr[p][3],
                      Bb + (uint32_t)(p * 16 * PITCH + ks * 32));
#pragma unroll
            for (int mi = 0; mi < 4; mi++)
#pragma unroll
                for (int nj = 0; nj < 4; nj++) {
                    const uint32_t* bp = bfr[nj >> 1];
                    uint32_t b0 = (nj & 1) ? bp[2] : bp[0];
                    uint32_t b1 = (nj & 1) ? bp[3] : bp[1];
                    mma_s8(acc[mi][nj], a[mi][0], a[mi][1], a[mi][2], a[mi][3], b0, b1);
                }
        }
    }

    // ---- epilogue: requant, float32 output, direct stores ----
    float sc[4][2];
    int bi[4][2];
#pragma unroll
    for (int nj = 0; nj < 4; nj++) {
        int co = co0 + wn * 32 + nj * 8 + tig * 2;
#pragma unroll
        for (int e = 0; e < 2; e++) {
            bi[nj][e] = g_bias[co + e];
            sc[nj][e] = g_scale[co + e];
        }
    }

#pragma unroll
    for (int mi = 0; mi < 4; mi++) {
        int pixbase = p0 + wm * 64 + mi * 16;
#pragma unroll
        for (int half = 0; half < 2; half++) {
            int pix = pixbase + g + half * 8;
            int n = pix / HW, sp = pix % HW;
            size_t obase = (size_t)n * (COUT * HW) + sp;
#pragma unroll
            for (int nj = 0; nj < 4; nj++) {
                int co = co0 + wn * 32 + nj * 8 + tig * 2;
#pragma unroll
                for (int e = 0; e < 2; e++) {
                    int a = acc[mi][nj][half * 2 + e] + bi[nj][e];
                    float y = __fadd_rn(__fmul_rn((float)a, sc[nj][e]), -2.0f);
                    y = rintf(y);
                    y = fminf(fmaxf(y, -128.0f), 127.0f);
                    out[obase + (size_t)(co + e) * HW] = y;
                }
            }
        }
    }
#undef ABUF
#undef BBUF
#undef LOAD_STAGE
}

// ---------------------------------------------------------------------------
extern "C" void kernel_launch(void* const* d_in, const int* in_sizes, int n_in,
                              void* d_out, int out_size) {
    int idx_sorted[8];
    int n = (n_in < 8) ? n_in : 8;
    for (int i = 0; i < n; i++) idx_sorted[i] = i;
    for (int i = 0; i < n; i++)
        for (int j = i + 1; j < n; j++)
            if (in_sizes[idx_sorted[j]] > in_sizes[idx_sorted[i]]) {
                int tmp = idx_sorted[i]; idx_sorted[i] = idx_sorted[j]; idx_sorted[j] = tmp;
            }
    const void* x = d_in[idx_sorted[0]];
    const void* w = d_in[idx_sorted[1]];
    int ia = idx_sorted[2], ib = idx_sorted[3];
    if (ia > ib) { int tmp = ia; ia = ib; ib = tmp; }
    const void* ap = d_in[ia];
    const void* bp = d_in[ib];

    static int smem_set = 0;
    if (!smem_set) {
        cudaFuncSetAttribute(conv_kernel, cudaFuncAttributeMaxDynamicSharedMemorySize,
                             SMEM_TOTAL);
        smem_set = 1;
    }

    probe_prep_kernel<<<1, 256>>>(x, w, ap, bp);
    pack_w_kernel<<<COUT / 2, 256>>>(w);
    pack_x_kernel<<<N_ * 28, 512>>>(x);

    dim3 grid((N_ * HW) / BM, COUT / BN);   // (784, 2)
    conv_kernel<<<grid, 256, SMEM_TOTAL>>>((float*)d_out);
}

// round 17
// speedup vs baseline: 1.1726x; 1.0793x over previous
#include <cuda_runtime.h>
#include <cuda_bf16.h>
#include <cuda_fp16.h>
#include <cstdint>
#include <math.h>

// ---------------------------------------------------------------------------
// QuantizedConv2d: N=32, Cin=128, H=W=56, Cout=256, 3x3, stride 1, pad 1
// pad value = IN_ZP = 3. Per-channel requant epilogue, float32 output.
//
// Round 17: R13 kernels byte-identical (best: 139.6us). ONE change, in the
// launcher: pack_w runs on a second stream concurrently with pack_x
// (fork-join with events — graph-capturable), hiding its ~4us.
// ---------------------------------------------------------------------------

#define N_    32
#define CIN   128
#define H_    56
#define W_    56
#define COUT  256
#define HW    (H_ * W_)
#define HP    58
#define WP    58

#define BM 128
#define BN 128
#define STAGES 9               // one per 3x3 tap, 128 B of K each
#define PITCH 144              // 128 B data + 16 B pad per row
#define STAGE_BYTES (256 * PITCH)          // A 128 rows + B 128 rows
#define SMEM_TOTAL (3 * STAGE_BYTES)       // 110592 B dynamic

// dtype codes: 0=int8, 1=int32, 2=float32, 3=bf16, 4=f16, 5=f64
__device__ int g_dt_x, g_dt_w, g_dt_b, g_dt_s, g_swap;
__device__ int g_bias[COUT];
__device__ float g_scale[COUT];

__device__ int8_t g_xpad[(size_t)N_ * HP * WP * CIN];   // NHWC padded, pad = 3
__device__ int8_t g_wt[(size_t)9 * COUT * CIN];         // [kpos][cout][cin]

// ---------------------------------------------------------------------------
__device__ __forceinline__ float bf_val(uint32_t h) { return __int_as_float(h << 16); }
__device__ __forceinline__ float h_val(uint32_t h) {
    return __half2float(__ushort_as_half((unsigned short)h));
}
__device__ __forceinline__ bool int_ok(float g) { return g == rintf(g) && fabsf(g) <= 4096.f; }
__device__ __forceinline__ bool sc_ok(float g) { return g > 1e-5f && g < 0.5f; }

// Warp-parallel probe: warp b probes buffer b (shfl-reduced counts, no atomics),
// then one barrier, then 256-thread bias/scale prep.  (R13 verbatim)
__global__ void probe_prep_kernel(const void* xp, const void* wp,
                                  const void* ap, const void* bp) {
    __shared__ int s_dt[4], s_scl[4], s_sdt[4];
    int t = threadIdx.x;
    int warp = t >> 5, lane = t & 31;

    if (warp < 4) {
        const void* bufs[4] = {xp, wp, ap, bp};
        const uint32_t* buf = (const uint32_t*)bufs[warp];
        const int NW = (warp < 2) ? 256 : 64;
        const int per = NW >> 5;              // words per lane: 8 or 2

        int cnt[9] = {0, 0, 0, 0, 0, 0, 0, 0, 0};
        for (int i = 0; i < per; i++) {
            uint32_t u = buf[lane * per + i];
            float f = __int_as_float(u);
            uint32_t hi = u >> 16, lo = u & 0xFFFFu;
            if (u == 0u || int_ok(f)) cnt[0]++;
            { int s = (int)u; if (s >= -4096 && s <= 4096) cnt[1]++; }
            if ((hi == 0u || int_ok(bf_val(hi))) && (lo == 0u || int_ok(bf_val(lo)))) cnt[2]++;
            if ((hi == 0u || int_ok(h_val(hi))) && (lo == 0u || int_ok(h_val(lo)))) cnt[3]++;
            if (sc_ok(f)) cnt[5]++;
            if (sc_ok(bf_val(hi)) && sc_ok(bf_val(lo))) cnt[6]++;
            if (sc_ok(h_val(hi)) && sc_ok(h_val(lo))) cnt[7]++;
        }
        const double* bufd = (const double*)buf;
        for (int i = 0; i < (per >> 1); i++) {
            double d = bufd[lane * (per >> 1) + i];
            if (d == rint(d) && fabs(d) <= 4096.0) cnt[4]++;
            if (d > 1e-5 && d < 0.5) cnt[8]++;
        }
#pragma unroll
        for (int c = 0; c < 9; c++)
#pragma unroll
            for (int o = 16; o > 0; o >>= 1)
                cnt[c] += __shfl_down_sync(0xFFFFFFFFu, cnt[c], o);

        if (lane == 0) {
            int th = NW - NW / 16, th2 = NW / 2 - NW / 32;
            s_dt[warp] = (cnt[0] >= th) ? 2 : (cnt[1] >= th) ? 1 : (cnt[2] >= th) ? 3
                       : (cnt[3] >= th) ? 4 : (cnt[4] >= th2) ? 5 : 0;
            s_scl[warp] = (cnt[5] >= th) || (cnt[6] >= th) || (cnt[7] >= th) || (cnt[8] >= th2);
            s_sdt[warp] = (cnt[5] >= th) ? 2 : (cnt[6] >= th) ? 3 : (cnt[7] >= th) ? 4
                        : (cnt[8] >= th2) ? 5 : 2;
        }
    }
    __syncthreads();

    int swap = (s_scl[2] && !s_scl[3]) ? 1 : 0;
    int dtb = swap ? s_dt[3] : s_dt[2];
    int dtsv = swap ? s_sdt[2] : s_sdt[3];
    if (t == 0) {
        g_dt_x = s_dt[0];
        g_dt_w = s_dt[1];
        g_swap = swap;
        g_dt_b = dtb;
        g_dt_s = dtsv;
    }

    // ---- prep bias + scale (one channel per thread) ----
    const void* BP = swap ? bp : ap;
    const void* WS = swap ? ap : bp;
    int i = t;
    int v;
    if (dtb == 2)      v = (int)rintf(((const float*)BP)[i]);
    else if (dtb == 3) v = (int)rintf(__bfloat162float(((const __nv_bfloat16*)BP)[i]));
    else if (dtb == 4) v = (int)rintf(__half2float(((const __half*)BP)[i]));
    else if (dtb == 5) v = (int)rint(((const double*)BP)[i]);
    else               v = ((const int*)BP)[i];
    g_bias[i] = v;

    float wsv;
    if (dtsv == 3)      wsv = __bfloat162float(((const __nv_bfloat16*)WS)[i]);
    else if (dtsv == 4) wsv = __half2float(((const __half*)WS)[i]);
    else if (dtsv == 5) wsv = (float)((const double*)WS)[i];
    else                wsv = ((const float*)WS)[i];
    g_scale[i] = __fdiv_rn(__fmul_rn(0.05f, wsv), 0.1f);   // reference op order
}

__device__ __forceinline__ int8_t load_elem(const void* p, int dt, size_t i) {
    if (dt == 2) return (int8_t)(int)rintf(((const float*)p)[i]);
    if (dt == 1) return (int8_t)((const int*)p)[i];
    if (dt == 3) return (int8_t)(int)rintf(__bfloat162float(((const __nv_bfloat16*)p)[i]));
    if (dt == 4) return (int8_t)(int)rintf(__half2float(((const __half*)p)[i]));
    if (dt == 5) return (int8_t)(int)rint(((const double*)p)[i]);
    return ((const int8_t*)p)[i];
}

// NCHW (any dtype) -> padded NHWC int8; one block per (n, 2 rows of h).
// Also writes the pad border (value 3).  (R13 verbatim)
__global__ void pack_x_kernel(const void* xv) {
    __shared__ int8_t s[2][CIN * 57];
    int nh2 = blockIdx.x;           // n * 28 + h2
    int n = nh2 / 28, h2 = nh2 % 28;
    int h0 = h2 * 2;
    int t = threadIdx.x;            // 512
    int dt = g_dt_x;

    int4 pv; pv.x = pv.y = pv.z = pv.w = 0x03030303;
    if (t < 32) {                   // w=0 / w=57 pads for this block's 2 rows
        int row = t >> 4;
        int side = (t >> 3) & 1;
        int k = t & 7;
        size_t off = ((size_t)(n * HP + h0 + row + 1) * WP + side * 57) * CIN
                     + (size_t)k * 16;
        *(int4*)(g_xpad + off) = pv;
    }
    if (h2 == 0 || h2 == 27) {      // full pad row h=0 or h=57
        int hsel = (h2 == 0) ? 0 : 57;
        size_t base = (size_t)(n * HP + hsel) * WP * CIN;
        for (int i = t; i < 464; i += 512)
            *(int4*)(g_xpad + base + (size_t)i * 16) = pv;
    }

    if (dt == 2) {
        const float4* xf = (const float4*)xv;
        for (int idx = t; idx < 2 * CIN * 14; idx += 512) {
            int row = idx / (CIN * 14), r = idx % (CIN * 14);
            int ci = r / 14, w4 = r % 14;
            float4 v = xf[((size_t)(n * CIN + ci) * H_ + h0 + row) * 14 + w4];
            int8_t* sp = s[row] + ci * 57 + w4 * 4;
            sp[0] = (int8_t)(int)rintf(v.x);
            sp[1] = (int8_t)(int)rintf(v.y);
            sp[2] = (int8_t)(int)rintf(v.z);
            sp[3] = (int8_t)(int)rintf(v.w);
        }
    } else {
        for (int idx = t; idx < 2 * CIN * W_; idx += 512) {
            int row = idx / (CIN * W_), r = idx % (CIN * W_);
            int ci = r / W_, w = r % W_;
            size_t gi = ((size_t)(n * CIN + ci) * H_ + h0 + row) * W_ + w;
            s[row][ci * 57 + w] = load_elem(xv, dt, gi);
        }
    }
    __syncthreads();

    for (int idx = t; idx < 2 * W_ * (CIN / 4); idx += 512) {
        int row = idx / (W_ * 32), r = idx % (W_ * 32);
        int w = r / 32, c4 = r % 32;
        const int8_t* sr = s[row];
        unsigned b0 = (unsigned char)sr[(c4 * 4 + 0) * 57 + w];
        unsigned b1 = (unsigned char)sr[(c4 * 4 + 1) * 57 + w];
        unsigned b2 = (unsigned char)sr[(c4 * 4 + 2) * 57 + w];
        unsigned b3 = (unsigned char)sr[(c4 * 4 + 3) * 57 + w];
        int8_t* dst = g_xpad + ((size_t)(n * HP + h0 + row + 1) * WP + 1) * CIN;
        *(unsigned*)(dst + (size_t)w * CIN + c4 * 4) = b0 | (b1 << 8) | (b2 << 16) | (b3 << 24);
    }
}

// OIHW (any dtype) -> [kpos][cout][cin] int8.  (R13 verbatim)
__global__ void pack_w_kernel(const void* wv) {
    __shared__ int8_t sw[2][9][CIN];
    int co0 = blockIdx.x * 2;
    int t = threadIdx.x;
    int dt = g_dt_w;

    if (dt == 2) {
        const float4* wf = (const float4*)wv;
        for (int i = t; i < 576; i += 256) {
            int cl = i / 288, i4 = i % 288;
            float4 v = wf[(size_t)(co0 + cl) * 288 + i4];
            float vv[4] = {v.x, v.y, v.z, v.w};
            int e = i4 * 4;
#pragma unroll
            for (int j = 0; j < 4; j++) {
                int e2 = e + j;
                sw[cl][e2 % 9][e2 / 9] = (int8_t)(int)rintf(vv[j]);
            }
        }
    } else {
        for (int i = t; i < 2304; i += 256) {
            int cl = i / 1152, e = i % 1152;
            sw[cl][e % 9][e / 9] = load_elem(wv, dt, (size_t)(co0 + cl) * 1152 + e);
        }
    }
    __syncthreads();

    if (t < 144) {
        int cl = t / 72, r = t % 72;
        int kp = r / 8, c16 = r % 8;
        int4 v = *(const int4*)&sw[cl][kp][c16 * 16];
        *(int4*)(g_wt + (size_t)kp * (COUT * CIN) + (size_t)(co0 + cl) * CIN
                 + (size_t)c16 * 16) = v;
    }
}

// ---------------------------------------------------------------------------
__device__ __forceinline__ void cpasync16(uint32_t smem, const void* gptr) {
    asm volatile("cp.async.cg.shared.global [%0], [%1], 16;\n" :: "r"(smem), "l"(gptr));
}

__device__ __forceinline__ void ldsm4(uint32_t& r0, uint32_t& r1, uint32_t& r2, uint32_t& r3,
                                      uint32_t addr) {
    asm volatile("ldmatrix.sync.aligned.m8n8.x4.shared.b16 {%0,%1,%2,%3}, [%4];"
                 : "=r"(r0), "=r"(r1), "=r"(r2), "=r"(r3) : "r"(addr));
}

__device__ __forceinline__ void mma_s8(int* c, uint32_t a0, uint32_t a1, uint32_t a2, uint32_t a3,
                                       uint32_t b0, uint32_t b1) {
    asm volatile(
        "mma.sync.aligned.m16n8k32.row.col.s32.s8.s8.s32 "
        "{%0,%1,%2,%3}, {%4,%5,%6,%7}, {%8,%9}, {%0,%1,%2,%3};"
        : "+r"(c[0]), "+r"(c[1]), "+r"(c[2]), "+r"(c[3])
        : "r"(a0), "r"(a1), "r"(a2), "r"(a3), "r"(b0), "r"(b1));
}

__global__ __launch_bounds__(256, 2)
void conv_kernel(float* __restrict__ out) {
    extern __shared__ __align__(16) uint8_t smem_raw[];

    const int t = threadIdx.x;
    const int lane = t & 31;
    const int warp = t >> 5;           // 0..7
    const int wm = warp >> 2;          // 0..1 : 64-pixel half
    const int wn = warp & 3;           // 0..3 : 32-cout quarter
    const int g = lane >> 2;           // 0..7
    const int tig = lane & 3;          // 0..3
    const int p0 = blockIdx.x * BM;
    const int co0 = blockIdx.y * BN;

    const uint32_t smbase = (uint32_t)__cvta_generic_to_shared(smem_raw);

    const int q = t & 7;
    const int row0 = t >> 3;           // 0..31
    int arow[4], brow[4];
#pragma unroll
    for (int i = 0; i < 4; i++) {
        int row = row0 + i * 32;
        int p = p0 + row;
        int n = p / HW;
        int hw = p % HW;
        int h = hw / W_, w = hw % W_;
        arow[i] = ((n * HP + h) * WP + w) * CIN + q * 16;
        brow[i] = (co0 + row) * CIN + q * 16;
    }
    const uint32_t s_off = (uint32_t)(row0 * PITCH + q * 16);

    const uint32_t a_toff = (uint32_t)((wm * 64 + (lane & 15)) * PITCH + (lane >> 4) * 16);
    const uint32_t b_toff = (uint32_t)((wn * 32 + ((lane >> 4) & 1) * 8 + (lane & 7)) * PITCH
                                       + ((lane >> 3) & 1) * 16);

    int acc[4][4][4] = {};             // [mi][nj][reg]

#define ABUF(b) (smbase + (uint32_t)(b) * STAGE_BYTES)
#define BBUF(b) (smbase + (uint32_t)(b) * STAGE_BYTES + (uint32_t)(128 * PITCH))

#define LOAD_STAGE(S, BUF)                                                        \
    do {                                                                          \
        int kpos_ = (S);                                                          \
        int aoff_ = ((kpos_ / 3) * WP + kpos_ % 3) * CIN;                         \
        int boff_ = kpos_ * (COUT * CIN);                                         \
        uint32_t ab_ = ABUF(BUF) + s_off;                                         \
        uint32_t bb_ = BBUF(BUF) + s_off;                                         \
        _Pragma("unroll")                                                         \
        for (int i_ = 0; i_ < 4; i_++)                                            \
            cpasync16(ab_ + (uint32_t)(i_ * 32 * PITCH), g_xpad + arow[i_] + aoff_); \
        _Pragma("unroll")                                                         \
        for (int i_ = 0; i_ < 4; i_++)                                            \
            cpasync16(bb_ + (uint32_t)(i_ * 32 * PITCH), g_wt + brow[i_] + boff_);   \
        asm volatile("cp.async.commit_group;\n");                                 \
    } while (0)

    LOAD_STAGE(0, 0);
    LOAD_STAGE(1, 1);

#pragma unroll 1
    for (int s = 0; s < STAGES; s++) {
        if (s < STAGES - 1)
            asm volatile("cp.async.wait_group 1;\n");
        else
            asm volatile("cp.async.wait_group 0;\n");
        __syncthreads();               // stage s visible; stage s-1 consumers done

        if (s + 2 < STAGES)
            LOAD_STAGE(s + 2, (s + 2) % 3);

        const int buf = s % 3;
        const uint32_t Ab = ABUF(buf) + a_toff;
        const uint32_t Bb = BBUF(buf) + b_toff;

#pragma unroll
        for (int ks = 0; ks < 4; ks++) {
            uint32_t a[4][4];
#pragma unroll
            for (int mi = 0; mi < 4; mi++)
                ldsm4(a[mi][0], a[mi][1], a[mi][2], a[mi][3],
                      Ab + (uint32_t)(mi * 16 * PITCH + ks * 32));
            uint32_t bfr[2][4];
#pragma unroll
            for (int p = 0; p < 2; p++)
                ldsm4(bfr[p][0], bfr[p][1], bfr[p][2], bfr[p][3],
                      Bb + (uint32_t)(p * 16 * PITCH + ks * 32));
#pragma unroll
            for (int mi = 0; mi < 4; mi++)
#pragma unroll
                for (int nj = 0; nj < 4; nj++) {
                    const uint32_t* bp = bfr[nj >> 1];
                    uint32_t b0 = (nj & 1) ? bp[2] : bp[0];
                    uint32_t b1 = (nj & 1) ? bp[3] : bp[1];
                    mma_s8(acc[mi][nj], a[mi][0], a[mi][1], a[mi][2], a[mi][3], b0, b1);
                }
        }
    }

    // ---- epilogue: requant, float32 output, direct stores ----
    float sc[4][2];
    int bi[4][2];
#pragma unroll
    for (int nj = 0; nj < 4; nj++) {
        int co = co0 + wn * 32 + nj * 8 + tig * 2;
#pragma unroll
        for (int e = 0; e < 2; e++) {
            bi[nj][e] = g_bias[co + e];
            sc[nj][e] = g_scale[co + e];
        }
    }

#pragma unroll
    for (int mi = 0; mi < 4; mi++) {
        int pixbase = p0 + wm * 64 + mi * 16;
#pragma unroll
        for (int half = 0; half < 2; half++) {
            int pix = pixbase + g + half * 8;
            int n = pix / HW, sp = pix % HW;
            size_t obase = (size_t)n * (COUT * HW) + sp;
#pragma unroll
            for (int nj = 0; nj < 4; nj++) {
                int co = co0 + wn * 32 + nj * 8 + tig * 2;
#pragma unroll
                for (int e = 0; e < 2; e++) {
                    int a = acc[mi][nj][half * 2 + e] + bi[nj][e];
                    float y = __fadd_rn(__fmul_rn((float)a, sc[nj][e]), -2.0f);
                    y = rintf(y);
                    y = fminf(fmaxf(y, -128.0f), 127.0f);
                    out[obase + (size_t)(co + e) * HW] = y;
                }
            }
        }
    }
#undef ABUF
#undef BBUF
#undef LOAD_STAGE
}

// ---------------------------------------------------------------------------
extern "C" void kernel_launch(void* const* d_in, const int* in_sizes, int n_in,
                              void* d_out, int out_size) {
    int idx_sorted[8];
    int n = (n_in < 8) ? n_in : 8;
    for (int i = 0; i < n; i++) idx_sorted[i] = i;
    for (int i = 0; i < n; i++)
        for (int j = i + 1; j < n; j++)
            if (in_sizes[idx_sorted[j]] > in_sizes[idx_sorted[i]]) {
                int tmp = idx_sorted[i]; idx_sorted[i] = idx_sorted[j]; idx_sorted[j] = tmp;
            }
    const void* x = d_in[idx_sorted[0]];
    const void* w = d_in[idx_sorted[1]];
    int ia = idx_sorted[2], ib = idx_sorted[3];
    if (ia > ib) { int tmp = ia; ia = ib; ib = tmp; }
    const void* ap = d_in[ia];
    const void* bp = d_in[ib];

    // one-time setup (runs on the uncaptured correctness call first)
    static cudaStream_t s2 = nullptr;
    static cudaEvent_t e_fork = nullptr, e_join = nullptr;
    static int init_done = 0;
    if (!init_done) {
        cudaFuncSetAttribute(conv_kernel, cudaFuncAttributeMaxDynamicSharedMemorySize,
                             SMEM_TOTAL);
        cudaStreamCreateWithFlags(&s2, cudaStreamNonBlocking);
        cudaEventCreateWithFlags(&e_fork, cudaEventDisableTiming);
        cudaEventCreateWithFlags(&e_join, cudaEventDisableTiming);
        init_done = 1;
    }

    // probe -> fork {pack_w on s2  ||  pack_x on main} -> join -> conv
    probe_prep_kernel<<<1, 256>>>(x, w, ap, bp);
    cudaEventRecord(e_fork, 0);
    cudaStreamWaitEvent(s2, e_fork, 0);

    pack_w_kernel<<<COUT / 2, 256, 0, s2>>>(w);
    pack_x_kernel<<<N_ * 28, 512>>>(x);

    cudaEventRecord(e_join, s2);
    cudaStreamWaitEvent(0, e_join, 0);

    dim3 grid((N_ * HW) / BM, COUT / BN);   // (784, 2)
    conv_kernel<<<grid, 256, SMEM_TOTAL>>>((float*)d_out);
}